// round 1
// baseline (speedup 1.0000x reference)
#include <cuda_runtime.h>
#include <cuda_bf16.h>
#include <cstddef>

// Problem constants
#define NUM_C 1000
#define Dd    128
#define Mm    64
#define Bb    64
#define Ll    512
#define NROWS (Bb * Ll)   // 32768
#define TR    64          // rows per block in dense kernels
#define CH    16          // scan: steps of w staged per chunk

// Scratch (static device globals — allocation-free)
__device__ float g_w[NROWS * Mm];      // softmax weights        [row][m]
__device__ float g_e[NROWS * Dd];      // erase gate             [row][d]
__device__ float g_a[NROWS * Dd];      // add vector             [row][d]
__device__ float g_read[NROWS * Dd];   // read content           [row][d]

__device__ __forceinline__ float sigmoidf_(float x) {
    return 1.0f / (1.0f + __expf(-x));
}

// ---------------------------------------------------------------------------
// Kernel 1: gather k,v ; logits + softmax -> w ; e = sigmoid(v We + be),
//           a = tanh(v Wa + ba).  One block = 64 (b,t) rows, 256 threads.
// ---------------------------------------------------------------------------
__global__ __launch_bounds__(256) void k_pre(
    const int* __restrict__ q, const int* __restrict__ r,
    const float* __restrict__ Ek, const float* __restrict__ Ev,
    const float* __restrict__ Mk,
    const float* __restrict__ We, const float* __restrict__ be,
    const float* __restrict__ Wa, const float* __restrict__ ba)
{
    extern __shared__ float sm[];
    float* sK   = sm;                 // [TR][Dd]
    float* sV   = sm + TR * Dd;       // [TR][Dd]
    float* sMkT = sm + 2 * TR * Dd;   // [Dd][66]  (Mk transposed, padded)

    const int tid  = threadIdx.x;
    const int row0 = blockIdx.x * TR;

    // Gather k and v rows (float4, coalesced per row)
    for (int i = tid; i < TR * (Dd / 4); i += 256) {
        int rr = i >> 5;      // Dd/4 == 32
        int c4 = i & 31;
        int gr = row0 + rr;
        int qi = q[gr];
        int xi = qi + NUM_C * r[gr];
        ((float4*)(sK + rr * Dd))[c4] = ((const float4*)(Ek + (size_t)qi * Dd))[c4];
        ((float4*)(sV + rr * Dd))[c4] = ((const float4*)(Ev + (size_t)xi * Dd))[c4];
    }
    // Transpose Mk into shared: sMkT[j][s]
    for (int i = tid; i < Mm * Dd; i += 256) {
        int s = i >> 7;       // row of Mk
        int j = i & 127;      // col of Mk
        sMkT[j * 66 + s] = Mk[i];
    }
    __syncthreads();

    const int rg = tid >> 5;   // warp id: rows rg*8 .. rg*8+7
    const int cg = tid & 31;   // lane

    // ---- logits + softmax: each lane owns slots 2cg, 2cg+1 for 8 rows ----
    {
        float acc0[8], acc1[8];
        #pragma unroll
        for (int i = 0; i < 8; i++) { acc0[i] = 0.f; acc1[i] = 0.f; }
        for (int j = 0; j < Dd; j++) {
            float2 mk = *(const float2*)(sMkT + j * 66 + 2 * cg);
            #pragma unroll
            for (int i = 0; i < 8; i++) {
                float kj = sK[(rg * 8 + i) * Dd + j];   // warp-uniform broadcast
                acc0[i] = fmaf(kj, mk.x, acc0[i]);
                acc1[i] = fmaf(kj, mk.y, acc1[i]);
            }
        }
        #pragma unroll
        for (int i = 0; i < 8; i++) {
            float mx = fmaxf(acc0[i], acc1[i]);
            #pragma unroll
            for (int o = 16; o > 0; o >>= 1)
                mx = fmaxf(mx, __shfl_xor_sync(0xffffffffu, mx, o));
            float e0 = __expf(acc0[i] - mx);
            float e1 = __expf(acc1[i] - mx);
            float s = e0 + e1;
            #pragma unroll
            for (int o = 16; o > 0; o >>= 1)
                s += __shfl_xor_sync(0xffffffffu, s, o);
            float inv = 1.0f / s;
            float2 wv = make_float2(e0 * inv, e1 * inv);
            *(float2*)(g_w + (size_t)(row0 + rg * 8 + i) * Mm + 2 * cg) = wv;
        }
    }

    // ---- e / a: each lane owns cols 4cg..4cg+3 for 8 rows ----
    {
        float4 acce[8], acca[8];
        #pragma unroll
        for (int i = 0; i < 8; i++) {
            acce[i] = make_float4(0.f, 0.f, 0.f, 0.f);
            acca[i] = make_float4(0.f, 0.f, 0.f, 0.f);
        }
        for (int j = 0; j < Dd; j++) {
            float4 we = ((const float4*)(We + (size_t)j * Dd))[cg];
            float4 wa = ((const float4*)(Wa + (size_t)j * Dd))[cg];
            float vj[8];
            #pragma unroll
            for (int i = 0; i < 8; i++) vj[i] = sV[(rg * 8 + i) * Dd + j];
            #pragma unroll
            for (int i = 0; i < 8; i++) {
                acce[i].x = fmaf(vj[i], we.x, acce[i].x);
                acce[i].y = fmaf(vj[i], we.y, acce[i].y);
                acce[i].z = fmaf(vj[i], we.z, acce[i].z);
                acce[i].w = fmaf(vj[i], we.w, acce[i].w);
                acca[i].x = fmaf(vj[i], wa.x, acca[i].x);
                acca[i].y = fmaf(vj[i], wa.y, acca[i].y);
                acca[i].z = fmaf(vj[i], wa.z, acca[i].z);
                acca[i].w = fmaf(vj[i], wa.w, acca[i].w);
            }
        }
        float4 bev = ((const float4*)be)[cg];
        float4 bav = ((const float4*)ba)[cg];
        #pragma unroll
        for (int i = 0; i < 8; i++) {
            size_t row = (size_t)(row0 + rg * 8 + i);
            float4 ev, av;
            ev.x = sigmoidf_(acce[i].x + bev.x);
            ev.y = sigmoidf_(acce[i].y + bev.y);
            ev.z = sigmoidf_(acce[i].z + bev.z);
            ev.w = sigmoidf_(acce[i].w + bev.w);
            av.x = tanhf(acca[i].x + bav.x);
            av.y = tanhf(acca[i].y + bav.y);
            av.z = tanhf(acca[i].z + bav.z);
            av.w = tanhf(acca[i].w + bav.w);
            ((float4*)(g_e + row * Dd))[cg] = ev;
            ((float4*)(g_a + row * Dd))[cg] = av;
        }
    }
}

// ---------------------------------------------------------------------------
// Kernel 2: sequential memory scan. grid (64 batches, 2 d-halves).
// 256 threads: mg = tid&3 owns 16 m-rows, dl = tid>>2 owns one column.
// State Mv[16] in registers. Read-reduction via shfl within 4-lane groups.
// ---------------------------------------------------------------------------
__global__ __launch_bounds__(256) void k_scan(const float* __restrict__ Mv0)
{
    const int b    = blockIdx.x;
    const int half = blockIdx.y;
    const int tid  = threadIdx.x;
    const int mg   = tid & 3;
    const int dl   = tid >> 2;          // 0..63
    const int d    = half * 64 + dl;

    float Mv[16];
    #pragma unroll
    for (int i = 0; i < 16; i++)
        Mv[i] = Mv0[(mg * 16 + i) * Dd + d];

    __shared__ float sW[CH][Mm];

    const size_t rbase = (size_t)b * Ll;
    float ed = g_e[rbase * Dd + d];
    float ad = g_a[rbase * Dd + d];

    for (int c = 0; c < Ll / CH; c++) {
        __syncthreads();   // previous chunk's sW fully consumed
        for (int i = tid; i < CH * Mm; i += 256)
            sW[i >> 6][i & 63] = g_w[(rbase + (size_t)c * CH) * Mm + i];
        __syncthreads();

        for (int tt = 0; tt < CH; tt++) {
            size_t row  = rbase + (size_t)c * CH + tt;
            size_t nrow = (row + 1 < rbase + Ll) ? row + 1 : row;
            float edn = g_e[nrow * Dd + d];   // prefetch next step
            float adn = g_a[nrow * Dd + d];

            float rp = 0.f;
            #pragma unroll
            for (int k4 = 0; k4 < 4; k4++) {
                float4 w4 = ((const float4*)(sW[tt] + mg * 16))[k4];
                // element 0
                rp = fmaf(w4.x, Mv[k4 * 4 + 0], rp);
                float t0 = fmaf(Mv[k4 * 4 + 0], ed, -ad);
                Mv[k4 * 4 + 0] = fmaf(-w4.x, t0, Mv[k4 * 4 + 0]);
                // element 1
                rp = fmaf(w4.y, Mv[k4 * 4 + 1], rp);
                float t1 = fmaf(Mv[k4 * 4 + 1], ed, -ad);
                Mv[k4 * 4 + 1] = fmaf(-w4.y, t1, Mv[k4 * 4 + 1]);
                // element 2
                rp = fmaf(w4.z, Mv[k4 * 4 + 2], rp);
                float t2 = fmaf(Mv[k4 * 4 + 2], ed, -ad);
                Mv[k4 * 4 + 2] = fmaf(-w4.z, t2, Mv[k4 * 4 + 2]);
                // element 3
                rp = fmaf(w4.w, Mv[k4 * 4 + 3], rp);
                float t3 = fmaf(Mv[k4 * 4 + 3], ed, -ad);
                Mv[k4 * 4 + 3] = fmaf(-w4.w, t3, Mv[k4 * 4 + 3]);
            }
            rp += __shfl_xor_sync(0xffffffffu, rp, 1);
            rp += __shfl_xor_sync(0xffffffffu, rp, 2);
            if (mg == 0) g_read[row * Dd + d] = rp;

            ed = edn; ad = adn;
        }
    }
}

// ---------------------------------------------------------------------------
// Kernel 3: f = tanh([read | k] @ Wf + bf); p = sigmoid(f . Wp + bp)
// ---------------------------------------------------------------------------
__global__ __launch_bounds__(256) void k_post(
    const int* __restrict__ q,
    const float* __restrict__ Ek,
    const float* __restrict__ Wf, const float* __restrict__ bf,
    const float* __restrict__ Wp, const float* __restrict__ bp,
    float* __restrict__ out)
{
    extern __shared__ float sm[];
    float* sR = sm;             // [TR][Dd]
    float* sK = sm + TR * Dd;   // [TR][Dd]

    const int tid  = threadIdx.x;
    const int row0 = blockIdx.x * TR;

    for (int i = tid; i < TR * (Dd / 4); i += 256) {
        int rr = i >> 5;
        int c4 = i & 31;
        int gr = row0 + rr;
        int qi = q[gr];
        ((float4*)(sK + rr * Dd))[c4] = ((const float4*)(Ek + (size_t)qi * Dd))[c4];
        ((float4*)(sR + rr * Dd))[c4] = ((const float4*)(g_read + (size_t)gr * Dd))[c4];
    }
    __syncthreads();

    const int rg = tid >> 5;
    const int cg = tid & 31;

    float4 acc[8];
    #pragma unroll
    for (int i = 0; i < 8; i++) acc[i] = make_float4(0.f, 0.f, 0.f, 0.f);

    for (int j = 0; j < Dd; j++) {
        float4 wr = ((const float4*)(Wf + (size_t)j * Dd))[cg];
        float4 wk = ((const float4*)(Wf + (size_t)(Dd + j) * Dd))[cg];
        #pragma unroll
        for (int i = 0; i < 8; i++) {
            float rj = sR[(rg * 8 + i) * Dd + j];
            float kj = sK[(rg * 8 + i) * Dd + j];
            acc[i].x = fmaf(rj, wr.x, fmaf(kj, wk.x, acc[i].x));
            acc[i].y = fmaf(rj, wr.y, fmaf(kj, wk.y, acc[i].y));
            acc[i].z = fmaf(rj, wr.z, fmaf(kj, wk.z, acc[i].z));
            acc[i].w = fmaf(rj, wr.w, fmaf(kj, wk.w, acc[i].w));
        }
    }

    float4 bfv = ((const float4*)bf)[cg];
    float4 wp4 = ((const float4*)Wp)[cg];
    float bpv  = bp[0];

    #pragma unroll
    for (int i = 0; i < 8; i++) {
        float fx = tanhf(acc[i].x + bfv.x);
        float fy = tanhf(acc[i].y + bfv.y);
        float fz = tanhf(acc[i].z + bfv.z);
        float fw = tanhf(acc[i].w + bfv.w);
        float pp = fx * wp4.x + fy * wp4.y + fz * wp4.z + fw * wp4.w;
        #pragma unroll
        for (int o = 16; o > 0; o >>= 1)
            pp += __shfl_xor_sync(0xffffffffu, pp, o);
        if (cg == 0)
            out[row0 + rg * 8 + i] = sigmoidf_(pp + bpv);
    }
}

// ---------------------------------------------------------------------------
extern "C" void kernel_launch(void* const* d_in, const int* in_sizes, int n_in,
                              void* d_out, int out_size)
{
    const int*   q   = (const int*)  d_in[0];
    const int*   r   = (const int*)  d_in[1];
    const float* Ek  = (const float*)d_in[2];
    const float* Ev  = (const float*)d_in[3];
    const float* Mk  = (const float*)d_in[4];
    const float* Mv0 = (const float*)d_in[5];
    const float* We  = (const float*)d_in[6];
    const float* be  = (const float*)d_in[7];
    const float* Wa  = (const float*)d_in[8];
    const float* ba  = (const float*)d_in[9];
    const float* Wf  = (const float*)d_in[10];
    const float* bf  = (const float*)d_in[11];
    const float* Wp  = (const float*)d_in[12];
    const float* bp  = (const float*)d_in[13];
    float* out = (float*)d_out;

    const size_t smem1 = (size_t)(2 * TR * Dd + Dd * 66) * sizeof(float); // 99328 B
    const size_t smem3 = (size_t)(2 * TR * Dd) * sizeof(float);           // 65536 B
    cudaFuncSetAttribute(k_pre,  cudaFuncAttributeMaxDynamicSharedMemorySize, (int)smem1);
    cudaFuncSetAttribute(k_post, cudaFuncAttributeMaxDynamicSharedMemorySize, (int)smem3);

    k_pre <<<NROWS / TR, 256, smem1>>>(q, r, Ek, Ev, Mk, We, be, Wa, ba);
    k_scan<<<dim3(Bb, 2), 256>>>(Mv0);
    k_post<<<NROWS / TR, 256, smem3>>>(q, Ek, Wf, bf, Wp, bp, out);
}

// round 4
// speedup vs baseline: 1.2996x; 1.2996x over previous
#include <cuda_runtime.h>
#include <cuda_bf16.h>
#include <cstddef>

// Problem constants
#define NUM_C 1000
#define Dd    128
#define Mm    64
#define Bb    64
#define Ll    512
#define NROWS (Bb * Ll)   // 32768
#define TR    64          // rows per block in dense kernels
#define CH    16          // scan: steps staged per chunk

// Scratch (static device globals — allocation-free)
__device__ float g_w[NROWS * Mm];
__device__ float g_e[NROWS * Dd];
__device__ float g_a[NROWS * Dd];
__device__ float g_read[NROWS * Dd];

typedef unsigned long long u64;

__device__ __forceinline__ float sigmoidf_(float x) {
    return 1.0f / (1.0f + __expf(-x));
}
__device__ __forceinline__ u64 bcast2(float x) {
    u64 r; asm("mov.b64 %0, {%1,%1};" : "=l"(r) : "f"(x)); return r;
}
__device__ __forceinline__ u64 pack2(float x, float y) {
    u64 r; asm("mov.b64 %0, {%1,%2};" : "=l"(r) : "f"(x), "f"(y)); return r;
}
__device__ __forceinline__ u64 fma2(u64 a, u64 b, u64 c) {
    u64 d; asm("fma.rn.f32x2 %0, %1, %2, %3;" : "=l"(d) : "l"(a), "l"(b), "l"(c)); return d;
}
__device__ __forceinline__ float2 unpk(u64 v) {
    float2 f; asm("mov.b64 {%0,%1}, %2;" : "=f"(f.x), "=f"(f.y) : "l"(v)); return f;
}
__device__ __forceinline__ float hsum2(u64 v) {
    float2 f = unpk(v); return f.x + f.y;
}

// ---------------------------------------------------------------------------
// Kernel 1: gather k,v ; logits + softmax -> w ; e = sigmoid(v We + be),
//           a = tanh(v Wa + ba).  One block = 64 rows, 256 threads.
// ---------------------------------------------------------------------------
__global__ __launch_bounds__(256, 2) void k_pre(
    const int* __restrict__ q, const int* __restrict__ r,
    const float* __restrict__ Ek, const float* __restrict__ Ev,
    const float* __restrict__ Mk,
    const float* __restrict__ We, const float* __restrict__ be,
    const float* __restrict__ Wa, const float* __restrict__ ba)
{
    extern __shared__ float sm[];
    float* sK   = sm;                 // [TR][Dd]
    float* sV   = sm + TR * Dd;       // [TR][Dd]
    float* sMkP = sm + 2 * TR * Dd;   // [64 jp][64 slots x float2]

    const int tid  = threadIdx.x;
    const int row0 = blockIdx.x * TR;

    // Gather k and v rows (float4, coalesced per row)
    for (int i = tid; i < TR * (Dd / 4); i += 256) {
        int rr = i >> 5;      // Dd/4 == 32
        int c4 = i & 31;
        int gr = row0 + rr;
        int qi = q[gr];
        int xi = qi + NUM_C * r[gr];
        ((float4*)(sK + rr * Dd))[c4] = ((const float4*)(Ek + (size_t)qi * Dd))[c4];
        ((float4*)(sV + rr * Dd))[c4] = ((const float4*)(Ev + (size_t)xi * Dd))[c4];
    }
    // Mk pre-paired over j: sMkP[jp][s] = (Mk[s][2jp], Mk[s][2jp+1])
    for (int i = tid; i < Mm * (Dd / 2); i += 256) {
        int s  = i & 63;
        int jp = i >> 6;
        ((float2*)sMkP)[jp * 64 + s] = *(const float2*)(Mk + (size_t)s * Dd + 2 * jp);
    }
    __syncthreads();

    const int rg = tid >> 5;   // warp: rows rg*8 .. rg*8+7
    const int cg = tid & 31;

    // ---- logits + softmax: lane owns slots 2cg, 2cg+1 for 8 rows ----
    {
        u64 acc0[8], acc1[8];
        #pragma unroll
        for (int i = 0; i < 8; i++) { acc0[i] = 0ull; acc1[i] = 0ull; }
        for (int jp = 0; jp < Dd / 2; jp++) {
            float4 mk4 = ((const float4*)(sMkP + jp * 128))[cg];
            u64 m0 = pack2(mk4.x, mk4.y);
            u64 m1 = pack2(mk4.z, mk4.w);
            #pragma unroll
            for (int i = 0; i < 8; i++) {
                u64 k2 = *(const u64*)(sK + (rg * 8 + i) * Dd + 2 * jp);
                acc0[i] = fma2(k2, m0, acc0[i]);
                acc1[i] = fma2(k2, m1, acc1[i]);
            }
        }
        #pragma unroll
        for (int i = 0; i < 8; i++) {
            float l0 = hsum2(acc0[i]);
            float l1 = hsum2(acc1[i]);
            float mx = fmaxf(l0, l1);
            #pragma unroll
            for (int o = 16; o > 0; o >>= 1)
                mx = fmaxf(mx, __shfl_xor_sync(0xffffffffu, mx, o));
            float e0 = __expf(l0 - mx);
            float e1 = __expf(l1 - mx);
            float s = e0 + e1;
            #pragma unroll
            for (int o = 16; o > 0; o >>= 1)
                s += __shfl_xor_sync(0xffffffffu, s, o);
            float inv = 1.0f / s;
            *(float2*)(g_w + (size_t)(row0 + rg * 8 + i) * Mm + 2 * cg) =
                make_float2(e0 * inv, e1 * inv);
        }
    }

    // ---- e / a: lane owns cols 4cg..4cg+3 (col-pair f32x2 accumulators) ----
    {
        u64 eA[8], eB[8], aA[8], aB[8];
        #pragma unroll
        for (int i = 0; i < 8; i++) { eA[i]=0ull; eB[i]=0ull; aA[i]=0ull; aB[i]=0ull; }

        for (int j = 0; j < Dd; j += 2) {
            float4 we0 = ((const float4*)(We + (size_t)j * Dd))[cg];
            float4 we1 = ((const float4*)(We + (size_t)(j + 1) * Dd))[cg];
            float4 wa0 = ((const float4*)(Wa + (size_t)j * Dd))[cg];
            float4 wa1 = ((const float4*)(Wa + (size_t)(j + 1) * Dd))[cg];
            u64 we0A = pack2(we0.x, we0.y), we0B = pack2(we0.z, we0.w);
            u64 we1A = pack2(we1.x, we1.y), we1B = pack2(we1.z, we1.w);
            u64 wa0A = pack2(wa0.x, wa0.y), wa0B = pack2(wa0.z, wa0.w);
            u64 wa1A = pack2(wa1.x, wa1.y), wa1B = pack2(wa1.z, wa1.w);
            #pragma unroll
            for (int i = 0; i < 8; i++) {
                float2 v2 = *(const float2*)(sV + (rg * 8 + i) * Dd + j);
                u64 b0 = bcast2(v2.x);
                u64 b1 = bcast2(v2.y);
                eA[i] = fma2(b0, we0A, eA[i]);  eB[i] = fma2(b0, we0B, eB[i]);
                eA[i] = fma2(b1, we1A, eA[i]);  eB[i] = fma2(b1, we1B, eB[i]);
                aA[i] = fma2(b0, wa0A, aA[i]);  aB[i] = fma2(b0, wa0B, aB[i]);
                aA[i] = fma2(b1, wa1A, aA[i]);  aB[i] = fma2(b1, wa1B, aB[i]);
            }
        }

        float4 bev = ((const float4*)be)[cg];
        float4 bav = ((const float4*)ba)[cg];
        #pragma unroll
        for (int i = 0; i < 8; i++) {
            size_t row = (size_t)(row0 + rg * 8 + i);
            float2 ea = unpk(eA[i]), eb = unpk(eB[i]);
            float2 aa = unpk(aA[i]), ab = unpk(aB[i]);
            float4 ev, av;
            ev.x = sigmoidf_(ea.x + bev.x);
            ev.y = sigmoidf_(ea.y + bev.y);
            ev.z = sigmoidf_(eb.x + bev.z);
            ev.w = sigmoidf_(eb.y + bev.w);
            av.x = tanhf(aa.x + bav.x);
            av.y = tanhf(aa.y + bav.y);
            av.z = tanhf(ab.x + bav.z);
            av.w = tanhf(ab.y + bav.w);
            ((float4*)(g_e + row * Dd))[cg] = ev;
            ((float4*)(g_a + row * Dd))[cg] = av;
        }
    }
}

// ---------------------------------------------------------------------------
// Kernel 2: sequential memory scan. grid (64 batches, 2 d-halves).
// ---------------------------------------------------------------------------
__global__ __launch_bounds__(256) void k_scan(const float* __restrict__ Mv0)
{
    const int b    = blockIdx.x;
    const int half = blockIdx.y;
    const int tid  = threadIdx.x;
    const int mg   = tid & 3;
    const int dl   = tid >> 2;
    const int d    = half * 64 + dl;

    float Mv[16];
    #pragma unroll
    for (int i = 0; i < 16; i++)
        Mv[i] = Mv0[(mg * 16 + i) * Dd + d];

    __shared__ float sW[CH][Mm];
    __shared__ float sE[CH][64];
    __shared__ float sA[CH][64];

    const size_t rbase = (size_t)b * Ll;

    for (int c = 0; c < Ll / CH; c++) {
        __syncthreads();
        ((float4*)sW)[tid] = ((const float4*)(g_w + (rbase + (size_t)c * CH) * Mm))[tid];
        {
            int tt = tid >> 4;
            int c4 = tid & 15;
            size_t row = rbase + (size_t)c * CH + tt;
            ((float4*)(sE[tt]))[c4] = ((const float4*)(g_e + row * Dd + half * 64))[c4];
            ((float4*)(sA[tt]))[c4] = ((const float4*)(g_a + row * Dd + half * 64))[c4];
        }
        __syncthreads();

        #pragma unroll 4
        for (int tt = 0; tt < CH; tt++) {
            float ed = sE[tt][dl];
            float ad = sA[tt][dl];
            float rp0 = 0.f, rp1 = 0.f, rp2 = 0.f, rp3 = 0.f;

            float4 w0 = ((const float4*)(sW[tt] + mg * 16))[0];
            float4 w1 = ((const float4*)(sW[tt] + mg * 16))[1];
            float4 w2 = ((const float4*)(sW[tt] + mg * 16))[2];
            float4 w3 = ((const float4*)(sW[tt] + mg * 16))[3];

            #define STEP(W, RP, IDX) do {                         \
                RP = fmaf(W, Mv[IDX], RP);                        \
                float t_ = fmaf(Mv[IDX], ed, -ad);                \
                Mv[IDX] = fmaf(-(W), t_, Mv[IDX]);                \
            } while (0)

            STEP(w0.x, rp0, 0);  STEP(w0.y, rp1, 1);  STEP(w0.z, rp2, 2);  STEP(w0.w, rp3, 3);
            STEP(w1.x, rp0, 4);  STEP(w1.y, rp1, 5);  STEP(w1.z, rp2, 6);  STEP(w1.w, rp3, 7);
            STEP(w2.x, rp0, 8);  STEP(w2.y, rp1, 9);  STEP(w2.z, rp2, 10); STEP(w2.w, rp3, 11);
            STEP(w3.x, rp0, 12); STEP(w3.y, rp1, 13); STEP(w3.z, rp2, 14); STEP(w3.w, rp3, 15);
            #undef STEP

            float rp = (rp0 + rp1) + (rp2 + rp3);
            rp += __shfl_xor_sync(0xffffffffu, rp, 1);
            rp += __shfl_xor_sync(0xffffffffu, rp, 2);
            if (mg == 0)
                g_read[(rbase + (size_t)c * CH + tt) * Dd + d] = rp;
        }
    }
}

// ---------------------------------------------------------------------------
// Kernel 3: f = tanh([read | k] @ Wf + bf); p = sigmoid(f . Wp + bp)
// ---------------------------------------------------------------------------
__global__ __launch_bounds__(256, 2) void k_post(
    const int* __restrict__ q,
    const float* __restrict__ Ek,
    const float* __restrict__ Wf, const float* __restrict__ bf,
    const float* __restrict__ Wp, const float* __restrict__ bp,
    float* __restrict__ out)
{
    extern __shared__ float sm[];
    float* sR = sm;             // [TR][Dd]
    float* sK = sm + TR * Dd;   // [TR][Dd]

    const int tid  = threadIdx.x;
    const int row0 = blockIdx.x * TR;

    for (int i = tid; i < TR * (Dd / 4); i += 256) {
        int rr = i >> 5;
        int c4 = i & 31;
        int gr = row0 + rr;
        int qi = q[gr];
        ((float4*)(sK + rr * Dd))[c4] = ((const float4*)(Ek + (size_t)qi * Dd))[c4];
        ((float4*)(sR + rr * Dd))[c4] = ((const float4*)(g_read + (size_t)gr * Dd))[c4];
    }
    __syncthreads();

    const int rg = tid >> 5;
    const int cg = tid & 31;

    u64 ac0[8], ac1[8], ac2[8], ac3[8];
    #pragma unroll
    for (int i = 0; i < 8; i++) { ac0[i]=0ull; ac1[i]=0ull; ac2[i]=0ull; ac3[i]=0ull; }

    for (int j = 0; j < Dd; j += 2) {
        float4 wrA = ((const float4*)(Wf + (size_t)j * Dd))[cg];
        float4 wrB = ((const float4*)(Wf + (size_t)(j + 1) * Dd))[cg];
        float4 wkA = ((const float4*)(Wf + (size_t)(Dd + j) * Dd))[cg];
        float4 wkB = ((const float4*)(Wf + (size_t)(Dd + j + 1) * Dd))[cg];
        u64 wr0 = pack2(wrA.x, wrB.x), wr1 = pack2(wrA.y, wrB.y);
        u64 wr2 = pack2(wrA.z, wrB.z), wr3 = pack2(wrA.w, wrB.w);
        u64 wk0 = pack2(wkA.x, wkB.x), wk1 = pack2(wkA.y, wkB.y);
        u64 wk2 = pack2(wkA.z, wkB.z), wk3 = pack2(wkA.w, wkB.w);
        #pragma unroll
        for (int i = 0; i < 8; i++) {
            u64 rj2 = *(const u64*)(sR + (rg * 8 + i) * Dd + j);
            u64 kj2 = *(const u64*)(sK + (rg * 8 + i) * Dd + j);
            ac0[i] = fma2(rj2, wr0, ac0[i]);
            ac1[i] = fma2(rj2, wr1, ac1[i]);
            ac2[i] = fma2(rj2, wr2, ac2[i]);
            ac3[i] = fma2(rj2, wr3, ac3[i]);
            ac0[i] = fma2(kj2, wk0, ac0[i]);
            ac1[i] = fma2(kj2, wk1, ac1[i]);
            ac2[i] = fma2(kj2, wk2, ac2[i]);
            ac3[i] = fma2(kj2, wk3, ac3[i]);
        }
    }

    float4 bfv = ((const float4*)bf)[cg];
    float4 wp4 = ((const float4*)Wp)[cg];
    float bpv  = bp[0];

    #pragma unroll
    for (int i = 0; i < 8; i++) {
        float fx = tanhf(hsum2(ac0[i]) + bfv.x);
        float fy = tanhf(hsum2(ac1[i]) + bfv.y);
        float fz = tanhf(hsum2(ac2[i]) + bfv.z);
        float fw = tanhf(hsum2(ac3[i]) + bfv.w);
        float pp = fx * wp4.x + fy * wp4.y + fz * wp4.z + fw * wp4.w;
        #pragma unroll
        for (int o = 16; o > 0; o >>= 1)
            pp += __shfl_xor_sync(0xffffffffu, pp, o);
        if (cg == 0)
            out[row0 + rg * 8 + i] = sigmoidf_(pp + bpv);
    }
}

// ---------------------------------------------------------------------------
extern "C" void kernel_launch(void* const* d_in, const int* in_sizes, int n_in,
                              void* d_out, int out_size)
{
    const int*   q   = (const int*)  d_in[0];
    const int*   r   = (const int*)  d_in[1];
    const float* Ek  = (const float*)d_in[2];
    const float* Ev  = (const float*)d_in[3];
    const float* Mk  = (const float*)d_in[4];
    const float* Mv0 = (const float*)d_in[5];
    const float* We  = (const float*)d_in[6];
    const float* be  = (const float*)d_in[7];
    const float* Wa  = (const float*)d_in[8];
    const float* ba  = (const float*)d_in[9];
    const float* Wf  = (const float*)d_in[10];
    const float* bf  = (const float*)d_in[11];
    const float* Wp  = (const float*)d_in[12];
    const float* bp  = (const float*)d_in[13];
    float* out = (float*)d_out;

    const size_t smem1 = (size_t)(2 * TR * Dd + (Dd / 2) * Mm * 2) * sizeof(float); // 98304 B
    const size_t smem3 = (size_t)(2 * TR * Dd) * sizeof(float);                     // 65536 B
    cudaFuncSetAttribute(k_pre,  cudaFuncAttributeMaxDynamicSharedMemorySize, (int)smem1);
    cudaFuncSetAttribute(k_post, cudaFuncAttributeMaxDynamicSharedMemorySize, (int)smem3);

    k_pre <<<NROWS / TR, 256, smem1>>>(q, r, Ek, Ev, Mk, We, be, Wa, ba);
    k_scan<<<dim3(Bb, 2), 256>>>(Mv0);
    k_post<<<NROWS / TR, 256, smem3>>>(q, Ek, Wf, bf, Wp, bp, out);
}

// round 5
// speedup vs baseline: 1.6875x; 1.2984x over previous
#include <cuda_runtime.h>
#include <cuda_bf16.h>
#include <cstddef>

// Problem constants
#define NUM_C 1000
#define Dd    128
#define Mm    64
#define Bb    64
#define Ll    512
#define NROWS (Bb * Ll)   // 32768
#define CH    16          // scan: steps staged per chunk

// Scratch (static device globals — allocation-free)
__device__ float g_w[NROWS * Mm];
__device__ float g_e[NROWS * Dd];
__device__ float g_a[NROWS * Dd];
__device__ float g_read[NROWS * Dd];

typedef unsigned long long u64;

__device__ __forceinline__ float sigmoidf_(float x) {
    return 1.0f / (1.0f + __expf(-x));
}
__device__ __forceinline__ u64 bcast2(float x) {
    u64 r; asm("mov.b64 %0, {%1,%1};" : "=l"(r) : "f"(x)); return r;
}
__device__ __forceinline__ u64 pack2(float x, float y) {
    u64 r; asm("mov.b64 %0, {%1,%2};" : "=l"(r) : "f"(x), "f"(y)); return r;
}
__device__ __forceinline__ u64 fma2(u64 a, u64 b, u64 c) {
    u64 d; asm("fma.rn.f32x2 %0, %1, %2, %3;" : "=l"(d) : "l"(a), "l"(b), "l"(c)); return d;
}
__device__ __forceinline__ float2 unpk(u64 v) {
    float2 f; asm("mov.b64 {%0,%1}, %2;" : "=f"(f.x), "=f"(f.y) : "l"(v)); return f;
}
__device__ __forceinline__ float hsum2(u64 v) {
    float2 f = unpk(v); return f.x + f.y;
}

// ---------------------------------------------------------------------------
// Kernel 1a: logits + softmax -> w.   512 threads, 64 rows/block.
// Warp w owns 4 rows; lane owns memory slots 2cg, 2cg+1.
// ---------------------------------------------------------------------------
__global__ __launch_bounds__(512, 2) void k_w(
    const int* __restrict__ q,
    const float* __restrict__ Ek,
    const float* __restrict__ Mk)
{
    extern __shared__ float sm[];
    float* sK   = sm;                 // [64][Dd]  32 KB
    float* sMkP = sm + 64 * Dd;       // [64 jp][64 slots float2]  32 KB

    const int tid  = threadIdx.x;
    const int row0 = blockIdx.x * 64;

    for (int i = tid; i < 64 * (Dd / 4); i += 512) {
        int rr = i >> 5;
        int c4 = i & 31;
        int qi = q[row0 + rr];
        ((float4*)(sK + rr * Dd))[c4] = ((const float4*)(Ek + (size_t)qi * Dd))[c4];
    }
    for (int i = tid; i < Mm * (Dd / 2); i += 512) {
        int s  = i & 63;
        int jp = i >> 6;
        ((float2*)sMkP)[jp * 64 + s] = *(const float2*)(Mk + (size_t)s * Dd + 2 * jp);
    }
    __syncthreads();

    const int wid = tid >> 5;   // 0..15, rows wid*4..wid*4+3
    const int cg  = tid & 31;

    u64 acc0[4], acc1[4];
    #pragma unroll
    for (int i = 0; i < 4; i++) { acc0[i] = 0ull; acc1[i] = 0ull; }

    for (int jp = 0; jp < Dd / 2; jp++) {
        float4 mk4 = ((const float4*)(sMkP + jp * 128))[cg];
        u64 m0 = pack2(mk4.x, mk4.y);
        u64 m1 = pack2(mk4.z, mk4.w);
        #pragma unroll
        for (int i = 0; i < 4; i++) {
            u64 k2 = *(const u64*)(sK + (wid * 4 + i) * Dd + 2 * jp);
            acc0[i] = fma2(k2, m0, acc0[i]);
            acc1[i] = fma2(k2, m1, acc1[i]);
        }
    }
    #pragma unroll
    for (int i = 0; i < 4; i++) {
        float l0 = hsum2(acc0[i]);
        float l1 = hsum2(acc1[i]);
        float mx = fmaxf(l0, l1);
        #pragma unroll
        for (int o = 16; o > 0; o >>= 1)
            mx = fmaxf(mx, __shfl_xor_sync(0xffffffffu, mx, o));
        float e0 = __expf(l0 - mx);
        float e1 = __expf(l1 - mx);
        float s = e0 + e1;
        #pragma unroll
        for (int o = 16; o > 0; o >>= 1)
            s += __shfl_xor_sync(0xffffffffu, s, o);
        float inv = 1.0f / s;
        *(float2*)(g_w + (size_t)(row0 + wid * 4 + i) * Mm + 2 * cg) =
            make_float2(e0 * inv, e1 * inv);
    }
}

// ---------------------------------------------------------------------------
// Kernel 1b: e = sigmoid(v We + be), a = tanh(v Wa + ba).
// 256 threads, 32 rows/block (1024 blocks). Warp owns 4 rows; lane owns
// cols 4cg..4cg+3 as two f32x2 accumulators per output.
// ---------------------------------------------------------------------------
__global__ __launch_bounds__(256, 4) void k_ea(
    const int* __restrict__ q, const int* __restrict__ r,
    const float* __restrict__ Ev,
    const float* __restrict__ We, const float* __restrict__ be,
    const float* __restrict__ Wa, const float* __restrict__ ba)
{
    extern __shared__ float sm[];
    float* sV = sm;   // [32][Dd]  16 KB

    const int tid  = threadIdx.x;
    const int row0 = blockIdx.x * 32;

    for (int i = tid; i < 32 * (Dd / 4); i += 256) {
        int rr = i >> 5;
        int c4 = i & 31;
        int gr = row0 + rr;
        int xi = q[gr] + NUM_C * r[gr];
        ((float4*)(sV + rr * Dd))[c4] = ((const float4*)(Ev + (size_t)xi * Dd))[c4];
    }
    __syncthreads();

    const int wid = tid >> 5;   // 0..7, rows wid*4..wid*4+3
    const int cg  = tid & 31;

    u64 eA[4], eB[4], aA[4], aB[4];
    #pragma unroll
    for (int i = 0; i < 4; i++) { eA[i]=0ull; eB[i]=0ull; aA[i]=0ull; aB[i]=0ull; }

    for (int j = 0; j < Dd; j++) {
        float4 we = ((const float4*)(We + (size_t)j * Dd))[cg];
        float4 wa = ((const float4*)(Wa + (size_t)j * Dd))[cg];
        u64 weA = pack2(we.x, we.y), weB = pack2(we.z, we.w);
        u64 waA = pack2(wa.x, wa.y), waB = pack2(wa.z, wa.w);
        #pragma unroll
        for (int i = 0; i < 4; i++) {
            u64 b0 = bcast2(sV[(wid * 4 + i) * Dd + j]);
            eA[i] = fma2(b0, weA, eA[i]);
            eB[i] = fma2(b0, weB, eB[i]);
            aA[i] = fma2(b0, waA, aA[i]);
            aB[i] = fma2(b0, waB, aB[i]);
        }
    }

    float4 bev = ((const float4*)be)[cg];
    float4 bav = ((const float4*)ba)[cg];
    #pragma unroll
    for (int i = 0; i < 4; i++) {
        size_t row = (size_t)(row0 + wid * 4 + i);
        float2 ea = unpk(eA[i]), eb = unpk(eB[i]);
        float2 aa = unpk(aA[i]), ab = unpk(aB[i]);
        float4 ev, av;
        ev.x = sigmoidf_(ea.x + bev.x);
        ev.y = sigmoidf_(ea.y + bev.y);
        ev.z = sigmoidf_(eb.x + bev.z);
        ev.w = sigmoidf_(eb.y + bev.w);
        av.x = tanhf(aa.x + bav.x);
        av.y = tanhf(aa.y + bav.y);
        av.z = tanhf(ab.x + bav.z);
        av.w = tanhf(ab.y + bav.w);
        ((float4*)(g_e + row * Dd))[cg] = ev;
        ((float4*)(g_a + row * Dd))[cg] = av;
    }
}

// ---------------------------------------------------------------------------
// Kernel 2: sequential memory scan. grid (64 batches, 4 d-quarters), 256 thr.
// mg = tid&7 owns 8 m-rows; dl = tid>>3 owns one of 32 d-columns.
// ---------------------------------------------------------------------------
__global__ __launch_bounds__(256) void k_scan(const float* __restrict__ Mv0)
{
    const int b    = blockIdx.x;
    const int qtr  = blockIdx.y;
    const int tid  = threadIdx.x;
    const int mg   = tid & 7;
    const int dl   = tid >> 3;          // 0..31
    const int d    = qtr * 32 + dl;

    float Mv[8];
    #pragma unroll
    for (int i = 0; i < 8; i++)
        Mv[i] = Mv0[(mg * 8 + i) * Dd + d];

    __shared__ float sW[CH][Mm];
    __shared__ float sE[CH][32];
    __shared__ float sA[CH][32];

    const size_t rbase = (size_t)b * Ll;

    for (int c = 0; c < Ll / CH; c++) {
        __syncthreads();
        // stage w: CH*64 floats = 256 float4 — one per thread
        ((float4*)sW)[tid] = ((const float4*)(g_w + (rbase + (size_t)c * CH) * Mm))[tid];
        // stage e,a: 128 float4 each; threads 0-127 -> E, 128-255 -> A
        {
            int t2 = tid & 127;
            int tt = t2 >> 3;
            int c4 = t2 & 7;
            size_t row = rbase + (size_t)c * CH + tt;
            if (tid < 128)
                ((float4*)(sE[tt]))[c4] = ((const float4*)(g_e + row * Dd + qtr * 32))[c4];
            else
                ((float4*)(sA[tt]))[c4] = ((const float4*)(g_a + row * Dd + qtr * 32))[c4];
        }
        __syncthreads();

        #pragma unroll 4
        for (int tt = 0; tt < CH; tt++) {
            float ed = sE[tt][dl];
            float ad = sA[tt][dl];
            float rp0 = 0.f, rp1 = 0.f, rp2 = 0.f, rp3 = 0.f;

            float4 w0 = ((const float4*)(sW[tt] + mg * 8))[0];
            float4 w1 = ((const float4*)(sW[tt] + mg * 8))[1];

            #define STEP(W, RP, IDX) do {                         \
                RP = fmaf(W, Mv[IDX], RP);                        \
                float t_ = fmaf(Mv[IDX], ed, -ad);                \
                Mv[IDX] = fmaf(-(W), t_, Mv[IDX]);                \
            } while (0)

            STEP(w0.x, rp0, 0);  STEP(w0.y, rp1, 1);
            STEP(w0.z, rp2, 2);  STEP(w0.w, rp3, 3);
            STEP(w1.x, rp0, 4);  STEP(w1.y, rp1, 5);
            STEP(w1.z, rp2, 6);  STEP(w1.w, rp3, 7);
            #undef STEP

            float rp = (rp0 + rp1) + (rp2 + rp3);
            rp += __shfl_xor_sync(0xffffffffu, rp, 1);
            rp += __shfl_xor_sync(0xffffffffu, rp, 2);
            rp += __shfl_xor_sync(0xffffffffu, rp, 4);
            if (mg == 0)
                g_read[(rbase + (size_t)c * CH + tt) * Dd + d] = rp;
        }
    }
}

// ---------------------------------------------------------------------------
// Kernel 3: f = tanh([read | k] @ Wf + bf); p = sigmoid(f . Wp + bp)
// 256 threads, 32 rows/block. Warp owns 4 rows; j-parity f32x2 accumulators.
// ---------------------------------------------------------------------------
__global__ __launch_bounds__(256, 4) void k_post(
    const int* __restrict__ q,
    const float* __restrict__ Ek,
    const float* __restrict__ Wf, const float* __restrict__ bf,
    const float* __restrict__ Wp, const float* __restrict__ bp,
    float* __restrict__ out)
{
    extern __shared__ float sm[];
    float* sR = sm;             // [32][Dd]
    float* sK = sm + 32 * Dd;   // [32][Dd]

    const int tid  = threadIdx.x;
    const int row0 = blockIdx.x * 32;

    for (int i = tid; i < 32 * (Dd / 4); i += 256) {
        int rr = i >> 5;
        int c4 = i & 31;
        int gr = row0 + rr;
        int qi = q[gr];
        ((float4*)(sK + rr * Dd))[c4] = ((const float4*)(Ek + (size_t)qi * Dd))[c4];
        ((float4*)(sR + rr * Dd))[c4] = ((const float4*)(g_read + (size_t)gr * Dd))[c4];
    }
    __syncthreads();

    const int wid = tid >> 5;   // 0..7, rows wid*4..wid*4+3
    const int cg  = tid & 31;

    u64 ac0[4], ac1[4], ac2[4], ac3[4];
    #pragma unroll
    for (int i = 0; i < 4; i++) { ac0[i]=0ull; ac1[i]=0ull; ac2[i]=0ull; ac3[i]=0ull; }

    for (int j = 0; j < Dd; j += 2) {
        float4 wrA = ((const float4*)(Wf + (size_t)j * Dd))[cg];
        float4 wrB = ((const float4*)(Wf + (size_t)(j + 1) * Dd))[cg];
        float4 wkA = ((const float4*)(Wf + (size_t)(Dd + j) * Dd))[cg];
        float4 wkB = ((const float4*)(Wf + (size_t)(Dd + j + 1) * Dd))[cg];
        u64 wr0 = pack2(wrA.x, wrB.x), wr1 = pack2(wrA.y, wrB.y);
        u64 wr2 = pack2(wrA.z, wrB.z), wr3 = pack2(wrA.w, wrB.w);
        u64 wk0 = pack2(wkA.x, wkB.x), wk1 = pack2(wkA.y, wkB.y);
        u64 wk2 = pack2(wkA.z, wkB.z), wk3 = pack2(wkA.w, wkB.w);
        #pragma unroll
        for (int i = 0; i < 4; i++) {
            u64 rj2 = *(const u64*)(sR + (wid * 4 + i) * Dd + j);
            u64 kj2 = *(const u64*)(sK + (wid * 4 + i) * Dd + j);
            ac0[i] = fma2(rj2, wr0, ac0[i]);
            ac1[i] = fma2(rj2, wr1, ac1[i]);
            ac2[i] = fma2(rj2, wr2, ac2[i]);
            ac3[i] = fma2(rj2, wr3, ac3[i]);
            ac0[i] = fma2(kj2, wk0, ac0[i]);
            ac1[i] = fma2(kj2, wk1, ac1[i]);
            ac2[i] = fma2(kj2, wk2, ac2[i]);
            ac3[i] = fma2(kj2, wk3, ac3[i]);
        }
    }

    float4 bfv = ((const float4*)bf)[cg];
    float4 wp4 = ((const float4*)Wp)[cg];
    float bpv  = bp[0];

    #pragma unroll
    for (int i = 0; i < 4; i++) {
        float fx = tanhf(hsum2(ac0[i]) + bfv.x);
        float fy = tanhf(hsum2(ac1[i]) + bfv.y);
        float fz = tanhf(hsum2(ac2[i]) + bfv.z);
        float fw = tanhf(hsum2(ac3[i]) + bfv.w);
        float pp = fx * wp4.x + fy * wp4.y + fz * wp4.z + fw * wp4.w;
        #pragma unroll
        for (int o = 16; o > 0; o >>= 1)
            pp += __shfl_xor_sync(0xffffffffu, pp, o);
        if (cg == 0)
            out[row0 + wid * 4 + i] = sigmoidf_(pp + bpv);
    }
}

// ---------------------------------------------------------------------------
extern "C" void kernel_launch(void* const* d_in, const int* in_sizes, int n_in,
                              void* d_out, int out_size)
{
    const int*   q   = (const int*)  d_in[0];
    const int*   r   = (const int*)  d_in[1];
    const float* Ek  = (const float*)d_in[2];
    const float* Ev  = (const float*)d_in[3];
    const float* Mk  = (const float*)d_in[4];
    const float* Mv0 = (const float*)d_in[5];
    const float* We  = (const float*)d_in[6];
    const float* be  = (const float*)d_in[7];
    const float* Wa  = (const float*)d_in[8];
    const float* ba  = (const float*)d_in[9];
    const float* Wf  = (const float*)d_in[10];
    const float* bf  = (const float*)d_in[11];
    const float* Wp  = (const float*)d_in[12];
    const float* bp  = (const float*)d_in[13];
    float* out = (float*)d_out;

    const size_t smW  = (size_t)(64 * Dd + (Dd / 2) * Mm * 2) * sizeof(float); // 65536 B
    const size_t smEA = (size_t)(32 * Dd) * sizeof(float);                     // 16384 B
    const size_t smP  = (size_t)(2 * 32 * Dd) * sizeof(float);                 // 32768 B
    cudaFuncSetAttribute(k_w,    cudaFuncAttributeMaxDynamicSharedMemorySize, (int)smW);
    cudaFuncSetAttribute(k_ea,   cudaFuncAttributeMaxDynamicSharedMemorySize, (int)smEA);
    cudaFuncSetAttribute(k_post, cudaFuncAttributeMaxDynamicSharedMemorySize, (int)smP);

    k_w   <<<NROWS / 64, 512, smW>>>(q, Ek, Mk);
    k_ea  <<<NROWS / 32, 256, smEA>>>(q, r, Ev, We, be, Wa, ba);
    k_scan<<<dim3(Bb, 4), 256>>>(Mv0);
    k_post<<<NROWS / 32, 256, smP>>>(q, Ek, Wf, bf, Wp, bp, out);
}